// round 14
// baseline (speedup 1.0000x reference)
#include <cuda_runtime.h>
#include <cuda_fp16.h>
#include <math.h>
#include <stdint.h>

#define BB 128
#define RR 4608
#define NR 8                 // r per staged batch
#define NBATCH 4
#define NRB (NR*NBATCH)      // 32 r per CTA
#define NCTA (RR/NRB)        // 144
#define INV_B (1.0f/128.0f)
#define INV_R (1.0f/4608.0f)

// smem tile geometry (48-byte padded rows -> conflict-free fragment LDS)
#define XROW 48
#define XT_RL (128*XROW)     // 6144 B per rl
#define WT_RL (64*XROW)      // 3072 B per rl
#define BUF_BYTES (NR*XT_RL + NR*WT_RL)   // 73728
#define DSM_P0 BUF_BYTES
#define DSM_RT (2*BUF_BYTES)              // 147456 (double buffer)

typedef unsigned long long ull;

// fp16 copies of inputs (written by pass0 while it computes)
__device__ __half g_xh[(size_t)RR * BB * 16];    // [r][b][i]
__device__ __half g_wh[(size_t)RR * 64 * 16];    // [r][ko][i]
__device__ __half g_parth[NCTA][BB * 64];        // fp16 per-CTA partials
__device__ float g_Zf[4];
__device__ float g_v[2][BB * 64];
__device__ float g_b1[RR * 2];

// ---------------- f32x2 helpers ------------------------------------------
__device__ __forceinline__ ull pack2(float lo, float hi) {
    ull r; asm("mov.b64 %0, {%1, %2};" : "=l"(r) : "f"(lo), "f"(hi)); return r;
}
__device__ __forceinline__ void unpack2(ull v, float& lo, float& hi) {
    asm("mov.b64 {%0, %1}, %2;" : "=f"(lo), "=f"(hi) : "l"(v));
}
__device__ __forceinline__ ull fma2(ull a, ull b, ull c) {
    ull d; asm("fma.rn.f32x2 %0, %1, %2, %3;" : "=l"(d) : "l"(a), "l"(b), "l"(c));
    return d;
}

__device__ __forceinline__ uint32_t smem_u32(const void* p) {
    uint32_t a;
    asm("{ .reg .u64 t; cvta.to.shared.u64 t, %1; cvt.u32.u64 %0, t; }"
        : "=r"(a) : "l"(p));
    return a;
}

// ---------------- m16n8k16 f16 MMA ---------------------------------------
__device__ __forceinline__ void mma16816(float* d, const uint32_t* a,
                                         const uint32_t* b, const float* c) {
    asm volatile(
        "mma.sync.aligned.m16n8k16.row.col.f32.f16.f16.f32 "
        "{%0,%1,%2,%3}, {%4,%5,%6,%7}, {%8,%9}, {%10,%11,%12,%13};"
        : "=f"(d[0]), "=f"(d[1]), "=f"(d[2]), "=f"(d[3])
        : "r"(a[0]), "r"(a[1]), "r"(a[2]), "r"(a[3]),
          "r"(b[0]), "r"(b[1]),
          "f"(c[0]), "f"(c[1]), "f"(c[2]), "f"(c[3]));
}

__device__ __forceinline__ uint2 cvt4(float4 v) {
    __half2 lo = __float22half2_rn(make_float2(v.x, v.y));
    __half2 hi = __float22half2_rn(make_float2(v.z, v.w));
    uint2 o; o.x = *(uint32_t*)&lo; o.y = *(uint32_t*)&hi;
    return o;
}

// ---------------- cp.async helpers ----------------------------------------
__device__ __forceinline__ void cpa16(uint32_t dst, const void* src) {
    asm volatile("cp.async.cg.shared.global [%0], [%1], 16;"
                 :: "r"(dst), "l"(src) : "memory");
}
#define CPA_COMMIT() asm volatile("cp.async.commit_group;" ::: "memory")
#define CPA_WAIT1()  asm volatile("cp.async.wait_group 1;" ::: "memory")
#define CPA_WAIT0()  asm volatile("cp.async.wait_group 0;" ::: "memory")

// ---------------------------------------------------------------------------
// pass0 staging: LDG fp32 -> convert -> regs (issued one batch early)
// ---------------------------------------------------------------------------
struct StageRegs { uint2 xr[8]; uint2 wr[4]; };

__device__ __forceinline__ void ldg_conv(StageRegs& S,
                                         const float4* __restrict__ x4,
                                         const float4* __restrict__ w4,
                                         int r0, int t) {
    #pragma unroll
    for (int j = 0; j < 8; j++) {
        int idx = j * 512 + t;
        int rl = idx >> 9, rem = idx & 511, b = rem >> 2, q = rem & 3;
        S.xr[j] = cvt4(x4[((size_t)b * RR + r0 + rl) * 4 + q]);
    }
    #pragma unroll
    for (int j = 0; j < 4; j++) {
        int idx = j * 512 + t;
        int rl = idx >> 8, rem = idx & 255, ko = rem >> 2, q = rem & 3;
        S.wr[j] = cvt4(w4[((size_t)(r0 + rl) * 64 + ko) * 4 + q]);
    }
}

__device__ __forceinline__ void sts_and_copy(const StageRegs& S, char* xt, char* wt,
                                             int r0, int t) {
    #pragma unroll
    for (int j = 0; j < 8; j++) {
        int idx = j * 512 + t;
        int rl = idx >> 9, rem = idx & 511, b = rem >> 2, q = rem & 3;
        *(uint2*)(xt + rl * XT_RL + b * XROW + q * 8) = S.xr[j];
        ((uint2*)g_xh)[((size_t)(r0 + rl) * BB + b) * 4 + q] = S.xr[j];
    }
    #pragma unroll
    for (int j = 0; j < 4; j++) {
        int idx = j * 512 + t;
        int rl = idx >> 8, rem = idx & 255, ko = rem >> 2, q = rem & 3;
        *(uint2*)(wt + rl * WT_RL + ko * XROW + q * 8) = S.wr[j];
        ((uint2*)g_wh)[((size_t)(r0 + rl) * 64 + ko) * 4 + q] = S.wr[j];
    }
}

// routing staging: cp.async fp16 copies -> smem (no conversion, no regs)
__device__ __forceinline__ void stage_async(char* xt, char* wt, int r0, int t) {
    uint32_t xa = smem_u32(xt), wa = smem_u32(wt);
    #pragma unroll
    for (int j = 0; j < 4; j++) {        // 2048 x-chunks of 16B
        int idx = j * 512 + t;
        int rl = idx >> 8, rem = idx & 255, b = rem >> 1, q = idx & 1;
        cpa16(xa + rl * XT_RL + b * XROW + q * 16,
              g_xh + ((size_t)(r0 + rl) * BB + b) * 16 + q * 8);
    }
    #pragma unroll
    for (int j = 0; j < 2; j++) {        // 1024 w-chunks of 16B
        int idx = j * 512 + t;
        int rl = idx >> 7, ko = (idx >> 1) & 63, q = idx & 1;
        cpa16(wa + rl * WT_RL + ko * XROW + q * 16,
              g_wh + ((size_t)(r0 + rl) * 64 + ko) * 16 + q * 8);
    }
}

__device__ __forceinline__ void load_a(const char* xb, uint32_t* A) {
    A[0] = *(const uint32_t*)(xb);
    A[1] = *(const uint32_t*)(xb + 8 * XROW);
    A[2] = *(const uint32_t*)(xb + 16);
    A[3] = *(const uint32_t*)(xb + 8 * XROW + 16);
}

// ---------------------------------------------------------------------------
// Pass 0 (+fp16 copy writes), pipelined reg staging.
// ---------------------------------------------------------------------------
__global__ __launch_bounds__(512, 1) void pass0_mma(const float4* __restrict__ x4,
                                                    const float4* __restrict__ w4) {
    extern __shared__ char dsm[];
    char* xt = dsm;
    char* wt = dsm + NR * XT_RL;
    const int t = threadIdx.x, lane = t & 31, w = t >> 5;
    const int m = w & 7, kh = w >> 3;
    const int gp = lane >> 2, tig = lane & 3;
    const int xoff = (m * 16 + gp) * XROW + tig * 4;
    const int woff = (kh * 32 + gp) * XROW + tig * 4;

    float CF[4][4];
    #pragma unroll
    for (int nt = 0; nt < 4; nt++)
        #pragma unroll
        for (int c = 0; c < 4; c++) CF[nt][c] = 0.f;

    const int rc = blockIdx.x * NRB;
    StageRegs S;
    ldg_conv(S, x4, w4, rc, t);
    for (int bt = 0; bt < NBATCH; bt++) {
        if (bt) __syncthreads();                 // tile free from previous compute
        sts_and_copy(S, xt, wt, rc + bt * NR, t);
        __syncthreads();
        if (bt + 1 < NBATCH) ldg_conv(S, x4, w4, rc + (bt + 1) * NR, t);
        #pragma unroll
        for (int rl = 0; rl < NR; rl++) {
            uint32_t A[4];
            load_a(xt + rl * XT_RL + xoff, A);
            const char* wb = wt + rl * WT_RL + woff;
            #pragma unroll
            for (int nt = 0; nt < 4; nt++) {
                uint32_t Bf[2];
                Bf[0] = *(const uint32_t*)(wb + nt * 8 * XROW);
                Bf[1] = *(const uint32_t*)(wb + nt * 8 * XROW + 16);
                mma16816(CF[nt], A, Bf, CF[nt]);
            }
        }
    }
    __half* dst = g_parth[blockIdx.x];
    #pragma unroll
    for (int nt = 0; nt < 4; nt++) {
        const int ko = kh * 32 + nt * 8 + 2 * tig;
        const int b0 = m * 16 + gp;
        *(__half2*)&dst[b0 * 64 + ko] =
            __float22half2_rn(make_float2(CF[nt][0], CF[nt][1]));
        *(__half2*)&dst[(b0 + 8) * 64 + ko] =
            __float22half2_rn(make_float2(CF[nt][2], CF[nt][3]));
    }
}

// ---------------------------------------------------------------------------
// Routing pass (deferred softmax), cp.async double-buffered staging,
// retained C fragments, mini-batch of 4 rl.
// ---------------------------------------------------------------------------
__global__ __launch_bounds__(512, 1) void routing_mma(int pass) {
    extern __shared__ char dsm[];
    __shared__ float red[4][2][128];
    __shared__ float ebc[8];
    const int t = threadIdx.x, lane = t & 31, w = t >> 5;
    const int m = w & 7, kh = w >> 3;
    const int gp = lane >> 2, tig = lane & 3;
    const int xoff = (m * 16 + gp) * XROW + tig * 4;
    const int woff = (kh * 32 + gp) * XROW + tig * 4;

    ull v2[2][4];
    {
        const float* vp = g_v[pass];
        #pragma unroll
        for (int row = 0; row < 2; row++) {
            const int b = m * 16 + gp + row * 8;
            #pragma unroll
            for (int nt = 0; nt < 4; nt++) {
                float2 q = *(const float2*)&vp[b * 64 + kh * 32 + nt * 8 + 2 * tig];
                v2[row][nt] = pack2(q.x, q.y);
            }
        }
    }
    ull S2[2][4];
    #pragma unroll
    for (int row = 0; row < 2; row++)
        #pragma unroll
        for (int nt = 0; nt < 4; nt++) S2[row][nt] = 0ull;
    float zacc = 0.f;

    const int rc = blockIdx.x * NRB;
    stage_async(dsm, dsm + NR * XT_RL, rc, t);
    CPA_COMMIT();

    for (int bt = 0; bt < NBATCH; bt++) {
        char* buf = dsm + (bt & 1) * BUF_BYTES;
        char* xt = buf;
        char* wt = buf + NR * XT_RL;
        if (bt + 1 < NBATCH) {
            char* nbuf = dsm + ((bt + 1) & 1) * BUF_BYTES;
            stage_async(nbuf, nbuf + NR * XT_RL, rc + (bt + 1) * NR, t);
            CPA_COMMIT();
            CPA_WAIT1();
        } else {
            CPA_WAIT0();
        }
        __syncthreads();

        #pragma unroll
        for (int mini = 0; mini < 2; mini++) {
            float CF[4][4][4];   // [rlm][nt][c] retained across the e barrier

            #pragma unroll
            for (int rlm = 0; rlm < 4; rlm++) {
                const int rl = mini * 4 + rlm;
                uint32_t A[4];
                load_a(xt + rl * XT_RL + xoff, A);
                const char* wb = wt + rl * WT_RL + woff;
                ull d0 = 0ull, d1 = 0ull;
                #pragma unroll
                for (int nt = 0; nt < 4; nt++) {
                    uint32_t Bf[2];
                    Bf[0] = *(const uint32_t*)(wb + nt * 8 * XROW);
                    Bf[1] = *(const uint32_t*)(wb + nt * 8 * XROW + 16);
                    float* C = CF[rlm][nt];
                    C[0] = 0.f; C[1] = 0.f; C[2] = 0.f; C[3] = 0.f;
                    mma16816(C, A, Bf, C);
                    d0 = fma2(pack2(C[0], C[1]), v2[0][nt], d0);
                    d1 = fma2(pack2(C[2], C[3]), v2[1][nt], d1);
                }
                float l0, h0, l1, h1;
                unpack2(d0, l0, h0); unpack2(d1, l1, h1);
                float dr0 = l0 + h0, dr1 = l1 + h1;
                dr0 += __shfl_xor_sync(0xffffffffu, dr0, 1);
                dr0 += __shfl_xor_sync(0xffffffffu, dr0, 2);
                dr1 += __shfl_xor_sync(0xffffffffu, dr1, 1);
                dr1 += __shfl_xor_sync(0xffffffffu, dr1, 2);
                if (tig == 0) {
                    red[rlm][kh][m * 16 + gp]     = dr0;
                    red[rlm][kh][m * 16 + gp + 8] = dr1;
                }
            }
            __syncthreads();

            if (w < 8) {
                const int rlm = w >> 1, kk = w & 1;
                const float* rrow = red[rlm][kk];
                float s = rrow[lane] + rrow[lane + 32] +
                          rrow[lane + 64] + rrow[lane + 96];
                #pragma unroll
                for (int sh = 16; sh >= 1; sh >>= 1)
                    s += __shfl_xor_sync(0xffffffffu, s, sh);
                if (lane == 0) {
                    float bn = s * INV_B;
                    const int gi = (rc + bt * NR + mini * 4 + rlm) * 2 + kk;
                    if (pass) bn += g_b1[gi];
                    else      g_b1[gi] = bn;
                    float e = expf(bn);
                    ebc[rlm * 2 + kk] = e;
                    zacc += e;
                }
            }
            __syncthreads();

            #pragma unroll
            for (int rlm = 0; rlm < 4; rlm++) {
                const float e = ebc[rlm * 2 + kh];
                const ull e2 = pack2(e, e);
                #pragma unroll
                for (int nt = 0; nt < 4; nt++) {
                    const float* C = CF[rlm][nt];
                    S2[0][nt] = fma2(pack2(C[0], C[1]), e2, S2[0][nt]);
                    S2[1][nt] = fma2(pack2(C[2], C[3]), e2, S2[1][nt]);
                }
            }
        }
    }

    __half* dst = g_parth[blockIdx.x];
    #pragma unroll
    for (int nt = 0; nt < 4; nt++) {
        const int ko = kh * 32 + nt * 8 + 2 * tig;
        const int b0 = m * 16 + gp;
        float lo, hi;
        unpack2(S2[0][nt], lo, hi);
        *(__half2*)&dst[b0 * 64 + ko] = __float22half2_rn(make_float2(lo, hi));
        unpack2(S2[1][nt], lo, hi);
        *(__half2*)&dst[(b0 + 8) * 64 + ko] = __float22half2_rn(make_float2(lo, hi));
    }
    if (w < 8 && lane == 0) atomicAdd(&g_Zf[pass * 2 + (w & 1)], zacc);
}

// ---------------------------------------------------------------------------
// Squash: 128 blocks x 1024 threads, 2 capsules/block; 9 fp16 partials per
// thread (coalesced), smem tree over 16 groups, group-0 norms + squashes.
// mode 0 also zeroes the Z accumulators for this launch (block 0).
// ---------------------------------------------------------------------------
__global__ __launch_bounds__(1024) void squash_kernel(int mode, float* __restrict__ out) {
    __shared__ float sred[2][16][33];
    const int t = threadIdx.x;
    const int o = t & 31, g = (t >> 5) & 15, c2 = t >> 9;
    const int cap = blockIdx.x * 2 + c2;   // 0..255 = b*2+k
    const int k = cap & 1;
    if (mode == 0 && blockIdx.x == 0 && t < 4) g_Zf[t] = 0.f;
    const int base = cap * 32 + o;

    float s = 0.f;
    #pragma unroll
    for (int j = 0; j < 9; j++)            // 144 = 9*16
        s += __half2float(g_parth[j * 16 + g][base]);
    sred[c2][g][o] = s;
    __syncthreads();

    if (g == 0) {
        float sum = 0.f;
        #pragma unroll
        for (int j = 0; j < 16; j++) sum += sred[c2][j][o];
        if (mode == 0) sum *= INV_R;
        else           sum /= g_Zf[(mode - 1) * 2 + k];
        float sq = sum * sum;
        #pragma unroll
        for (int m = 16; m >= 1; m >>= 1) sq += __shfl_xor_sync(0xffffffffu, sq, m);
        const float f = sqrtf(sq) / (0.5f + sq);
        const float v = sum * f;
        if (mode == 2) out[base] = v;
        else           g_v[mode][base] = v;
    }
}

// ---------------------------------------------------------------------------
extern "C" void kernel_launch(void* const* d_in, const int* in_sizes, int n_in,
                              void* d_out, int out_size) {
    const float* x = (const float*)d_in[0];   // [128, 4608, 16]
    const float* W = (const float*)d_in[1];   // [1, 4608, 2, 32, 16]
    float* out = (float*)d_out;               // [128, 2, 32]

    cudaFuncSetAttribute(pass0_mma,
                         cudaFuncAttributeMaxDynamicSharedMemorySize, DSM_P0);
    cudaFuncSetAttribute(routing_mma,
                         cudaFuncAttributeMaxDynamicSharedMemorySize, DSM_RT);

    pass0_mma<<<NCTA, 512, DSM_P0>>>((const float4*)x, (const float4*)W);
    squash_kernel<<<128, 1024>>>(0, nullptr);
    routing_mma<<<NCTA, 512, DSM_RT>>>(0);
    squash_kernel<<<128, 1024>>>(1, nullptr);
    routing_mma<<<NCTA, 512, DSM_RT>>>(1);
    squash_kernel<<<128, 1024>>>(2, out);
}

// round 15
// speedup vs baseline: 1.1508x; 1.1508x over previous
#include <cuda_runtime.h>
#include <cuda_fp16.h>
#include <math.h>
#include <stdint.h>

#define BB 128
#define RR 4608
#define NR 8                 // r per staged batch
#define NBATCH 4
#define NRB (NR*NBATCH)      // 32 r per CTA
#define NCTA (RR/NRB)        // 144
#define INV_B (1.0f/128.0f)
#define INV_R (1.0f/4608.0f)

// smem tile geometry (48-byte padded rows -> conflict-free fragment LDS)
#define XROW 48
#define XT_RL (128*XROW)     // 6144 B per rl
#define WT_RL (64*XROW)      // 3072 B per rl
#define DSM_BYTES (NR*XT_RL + NR*WT_RL)   // 73728

typedef unsigned long long ull;

__device__ float g_part[NCTA][BB * 64];          // per-CTA partials (STG, no atomics)
__device__ float g_Zf[4];
__device__ float g_v[2][BB * 64];
__device__ float g_b1[RR * 2];

// ---------------- f32x2 helpers ------------------------------------------
__device__ __forceinline__ ull pack2(float lo, float hi) {
    ull r; asm("mov.b64 %0, {%1, %2};" : "=l"(r) : "f"(lo), "f"(hi)); return r;
}
__device__ __forceinline__ void unpack2(ull v, float& lo, float& hi) {
    asm("mov.b64 {%0, %1}, %2;" : "=f"(lo), "=f"(hi) : "l"(v));
}
__device__ __forceinline__ ull fma2(ull a, ull b, ull c) {
    ull d; asm("fma.rn.f32x2 %0, %1, %2, %3;" : "=l"(d) : "l"(a), "l"(b), "l"(c));
    return d;
}

// ---------------- m16n8k16 f16 MMA ---------------------------------------
__device__ __forceinline__ void mma16816(float* d, const uint32_t* a,
                                         const uint32_t* b, const float* c) {
    asm volatile(
        "mma.sync.aligned.m16n8k16.row.col.f32.f16.f16.f32 "
        "{%0,%1,%2,%3}, {%4,%5,%6,%7}, {%8,%9}, {%10,%11,%12,%13};"
        : "=f"(d[0]), "=f"(d[1]), "=f"(d[2]), "=f"(d[3])
        : "r"(a[0]), "r"(a[1]), "r"(a[2]), "r"(a[3]),
          "r"(b[0]), "r"(b[1]),
          "f"(c[0]), "f"(c[1]), "f"(c[2]), "f"(c[3]));
}

__device__ __forceinline__ uint2 cvt4(float4 v) {
    __half2 lo = __float22half2_rn(make_float2(v.x, v.y));
    __half2 hi = __float22half2_rn(make_float2(v.z, v.w));
    uint2 o; o.x = *(uint32_t*)&lo; o.y = *(uint32_t*)&hi;
    return o;
}

// ---------------------------------------------------------------------------
// Staging: read fp32 inputs (L2-hot after pass0), convert to fp16 tiles.
// ---------------------------------------------------------------------------
__device__ __forceinline__ void stage_conv(char* xt, char* wt,
                                           const float4* __restrict__ x4,
                                           const float4* __restrict__ w4,
                                           int r0, int t) {
    #pragma unroll
    for (int j = 0; j < 8; j++) {
        int idx = j * 512 + t;
        int rl = idx >> 9, rem = idx & 511, b = rem >> 2, q = rem & 3;
        uint2 u = cvt4(x4[((size_t)b * RR + r0 + rl) * 4 + q]);
        *(uint2*)(xt + rl * XT_RL + b * XROW + q * 8) = u;
    }
    #pragma unroll
    for (int j = 0; j < 4; j++) {
        int idx = j * 512 + t;
        int rl = idx >> 8, rem = idx & 255, ko = rem >> 2, q = rem & 3;
        uint2 u = cvt4(w4[((size_t)(r0 + rl) * 64 + ko) * 4 + q]);
        *(uint2*)(wt + rl * WT_RL + ko * XROW + q * 8) = u;
    }
}

__device__ __forceinline__ void load_a(const char* xb, uint32_t* A) {
    A[0] = *(const uint32_t*)(xb);
    A[1] = *(const uint32_t*)(xb + 8 * XROW);
    A[2] = *(const uint32_t*)(xb + 16);
    A[3] = *(const uint32_t*)(xb + 8 * XROW + 16);
}

// ---------------------------------------------------------------------------
// Pass 0: s0 partial = sum over 32 r of u_hat via C-frag accumulation.
// ---------------------------------------------------------------------------
__global__ __launch_bounds__(512, 1) void pass0_mma(const float4* __restrict__ x4,
                                                    const float4* __restrict__ w4) {
    extern __shared__ char dsm[];
    char* xt = dsm;
    char* wt = dsm + NR * XT_RL;
    const int t = threadIdx.x, lane = t & 31, w = t >> 5;
    const int m = w & 7, kh = w >> 3;
    const int gp = lane >> 2, tig = lane & 3;
    const int xoff = (m * 16 + gp) * XROW + tig * 4;
    const int woff = (kh * 32 + gp) * XROW + tig * 4;

    cudaTriggerProgrammaticLaunchCompletion();

    float CF[4][4];
    #pragma unroll
    for (int nt = 0; nt < 4; nt++)
        #pragma unroll
        for (int c = 0; c < 4; c++) CF[nt][c] = 0.f;

    const int rc = blockIdx.x * NRB;
    for (int bt = 0; bt < NBATCH; bt++) {
        if (bt) __syncthreads();
        stage_conv(xt, wt, x4, w4, rc + bt * NR, t);
        __syncthreads();
        #pragma unroll
        for (int rl = 0; rl < NR; rl++) {
            uint32_t A[4];
            load_a(xt + rl * XT_RL + xoff, A);
            const char* wb = wt + rl * WT_RL + woff;
            #pragma unroll
            for (int nt = 0; nt < 4; nt++) {
                uint32_t Bf[2];
                Bf[0] = *(const uint32_t*)(wb + nt * 8 * XROW);
                Bf[1] = *(const uint32_t*)(wb + nt * 8 * XROW + 16);
                mma16816(CF[nt], A, Bf, CF[nt]);
            }
        }
    }
    float* dst = g_part[blockIdx.x];
    #pragma unroll
    for (int nt = 0; nt < 4; nt++) {
        const int ko = kh * 32 + nt * 8 + 2 * tig;
        const int b0 = m * 16 + gp;
        *(float2*)&dst[b0 * 64 + ko]       = make_float2(CF[nt][0], CF[nt][1]);
        *(float2*)&dst[(b0 + 8) * 64 + ko] = make_float2(CF[nt][2], CF[nt][3]);
    }
}

// ---------------------------------------------------------------------------
// Routing pass (deferred softmax), retained C fragments. PDL: batch-0
// staging overlaps the preceding squash; gridsync before reading g_v.
// ---------------------------------------------------------------------------
__global__ __launch_bounds__(512, 1) void routing_mma(const float4* __restrict__ x4,
                                                      const float4* __restrict__ w4,
                                                      int pass) {
    extern __shared__ char dsm[];
    char* xt = dsm;
    char* wt = dsm + NR * XT_RL;
    __shared__ float red[4][2][128];
    __shared__ float ebc[8];
    const int t = threadIdx.x, lane = t & 31, w = t >> 5;
    const int m = w & 7, kh = w >> 3;
    const int gp = lane >> 2, tig = lane & 3;
    const int xoff = (m * 16 + gp) * XROW + tig * 4;
    const int woff = (kh * 32 + gp) * XROW + tig * 4;

    cudaTriggerProgrammaticLaunchCompletion();

    const int rc = blockIdx.x * NRB;
    // stage batch 0 (reads only x/W) BEFORE waiting on the squash producer
    stage_conv(xt, wt, x4, w4, rc, t);

    cudaGridDependencySynchronize();   // v (and b1 for pass 1) now valid

    // v fragments: v2[row][nt] covers (b=m*16+gp+row*8, ko=kh*32+nt*8+2*tig{,+1})
    ull v2[2][4];
    {
        const float* vp = g_v[pass];
        #pragma unroll
        for (int row = 0; row < 2; row++) {
            const int b = m * 16 + gp + row * 8;
            #pragma unroll
            for (int nt = 0; nt < 4; nt++) {
                float2 q = *(const float2*)&vp[b * 64 + kh * 32 + nt * 8 + 2 * tig];
                v2[row][nt] = pack2(q.x, q.y);
            }
        }
    }
    ull S2[2][4];
    #pragma unroll
    for (int row = 0; row < 2; row++)
        #pragma unroll
        for (int nt = 0; nt < 4; nt++) S2[row][nt] = 0ull;
    float zacc = 0.f;

    __syncthreads();   // batch-0 tiles staged

    for (int bt = 0; bt < NBATCH; bt++) {
        #pragma unroll
        for (int mini = 0; mini < 2; mini++) {
            float CF[4][4][4];   // [rlm][nt][c] retained across the e barrier

            // ---- sweep: u fragments + agreement dots ----
            #pragma unroll
            for (int rlm = 0; rlm < 4; rlm++) {
                const int rl = mini * 4 + rlm;
                uint32_t A[4];
                load_a(xt + rl * XT_RL + xoff, A);
                const char* wb = wt + rl * WT_RL + woff;
                ull d0 = 0ull, d1 = 0ull;
                #pragma unroll
                for (int nt = 0; nt < 4; nt++) {
                    uint32_t Bf[2];
                    Bf[0] = *(const uint32_t*)(wb + nt * 8 * XROW);
                    Bf[1] = *(const uint32_t*)(wb + nt * 8 * XROW + 16);
                    float* C = CF[rlm][nt];
                    C[0] = 0.f; C[1] = 0.f; C[2] = 0.f; C[3] = 0.f;
                    mma16816(C, A, Bf, C);
                    d0 = fma2(pack2(C[0], C[1]), v2[0][nt], d0);
                    d1 = fma2(pack2(C[2], C[3]), v2[1][nt], d1);
                }
                float l0, h0, l1, h1;
                unpack2(d0, l0, h0); unpack2(d1, l1, h1);
                float dr0 = l0 + h0, dr1 = l1 + h1;
                dr0 += __shfl_xor_sync(0xffffffffu, dr0, 1);
                dr0 += __shfl_xor_sync(0xffffffffu, dr0, 2);
                dr1 += __shfl_xor_sync(0xffffffffu, dr1, 1);
                dr1 += __shfl_xor_sync(0xffffffffu, dr1, 2);
                if (tig == 0) {
                    red[rlm][kh][m * 16 + gp]     = dr0;
                    red[rlm][kh][m * 16 + gp + 8] = dr1;
                }
            }
            __syncthreads();

            // ---- e stage: warps 0..7, one per (rlm, k) ----
            if (w < 8) {
                const int rlm = w >> 1, kk = w & 1;
                const float* rrow = red[rlm][kk];
                float s = rrow[lane] + rrow[lane + 32] +
                          rrow[lane + 64] + rrow[lane + 96];
                #pragma unroll
                for (int sh = 16; sh >= 1; sh >>= 1)
                    s += __shfl_xor_sync(0xffffffffu, s, sh);
                if (lane == 0) {
                    float bn = s * INV_B;
                    const int gi = (rc + bt * NR + mini * 4 + rlm) * 2 + kk;
                    if (pass) bn += g_b1[gi];
                    else      g_b1[gi] = bn;
                    float e = expf(bn);
                    ebc[rlm * 2 + kk] = e;
                    zacc += e;
                }
            }
            __syncthreads();

            // ---- weighted accumulation from retained fragments ----
            #pragma unroll
            for (int rlm = 0; rlm < 4; rlm++) {
                const float e = ebc[rlm * 2 + kh];
                const ull e2 = pack2(e, e);
                #pragma unroll
                for (int nt = 0; nt < 4; nt++) {
                    const float* C = CF[rlm][nt];
                    S2[0][nt] = fma2(pack2(C[0], C[1]), e2, S2[0][nt]);
                    S2[1][nt] = fma2(pack2(C[2], C[3]), e2, S2[1][nt]);
                }
            }
        }
        if (bt + 1 < NBATCH) {
            __syncthreads();
            stage_conv(xt, wt, x4, w4, rc + (bt + 1) * NR, t);
            __syncthreads();
        }
    }

    float* dst = g_part[blockIdx.x];
    #pragma unroll
    for (int nt = 0; nt < 4; nt++) {
        const int ko = kh * 32 + nt * 8 + 2 * tig;
        const int b0 = m * 16 + gp;
        float lo, hi;
        unpack2(S2[0][nt], lo, hi);
        *(float2*)&dst[b0 * 64 + ko] = make_float2(lo, hi);
        unpack2(S2[1][nt], lo, hi);
        *(float2*)&dst[(b0 + 8) * 64 + ko] = make_float2(lo, hi);
    }
    if (w < 8 && lane == 0) atomicAdd(&g_Zf[pass * 2 + (w & 1)], zacc);
}

// ---------------------------------------------------------------------------
// Squash: 128 blocks x 1024 threads, 2 capsules/block; 9 partials per
// thread (coalesced), smem tree over 16 groups, group-0 norms + squashes.
// mode 0 also zeroes the Z accumulators for this launch (block 0).
// ---------------------------------------------------------------------------
__global__ __launch_bounds__(1024) void squash_kernel(int mode, float* __restrict__ out) {
    __shared__ float sred[2][16][33];
    const int t = threadIdx.x;
    const int o = t & 31, g = (t >> 5) & 15, c2 = t >> 9;
    const int cap = blockIdx.x * 2 + c2;   // 0..255 = b*2+k
    const int k = cap & 1;
    const int base = cap * 32 + o;

    cudaTriggerProgrammaticLaunchCompletion();
    cudaGridDependencySynchronize();       // partials + Z complete

    if (mode == 0 && blockIdx.x == 0 && t < 4) g_Zf[t] = 0.f;

    float s = 0.f;
    #pragma unroll
    for (int j = 0; j < 9; j++)            // 144 = 9*16
        s += g_part[j * 16 + g][base];
    sred[c2][g][o] = s;
    __syncthreads();

    if (g == 0) {
        float sum = 0.f;
        #pragma unroll
        for (int j = 0; j < 16; j++) sum += sred[c2][j][o];
        if (mode == 0) sum *= INV_R;
        else           sum /= g_Zf[(mode - 1) * 2 + k];
        float sq = sum * sum;
        #pragma unroll
        for (int m = 16; m >= 1; m >>= 1) sq += __shfl_xor_sync(0xffffffffu, sq, m);
        const float f = sqrtf(sq) / (0.5f + sq);
        const float v = sum * f;
        if (mode == 2) out[base] = v;
        else           g_v[mode][base] = v;
    }
}

// ---------------------------------------------------------------------------
// Launch helpers: PDL-enabled launches with plain-launch fallback.
// ---------------------------------------------------------------------------
static inline cudaLaunchConfig_t make_cfg(dim3 g, dim3 b, size_t sm,
                                          cudaLaunchAttribute* a) {
    cudaLaunchConfig_t c{};
    c.gridDim = g; c.blockDim = b; c.dynamicSmemBytes = sm;
    c.stream = 0; c.attrs = a; c.numAttrs = 1;
    return c;
}

extern "C" void kernel_launch(void* const* d_in, const int* in_sizes, int n_in,
                              void* d_out, int out_size) {
    const float4* x = (const float4*)d_in[0];   // [128, 4608, 16]
    const float4* W = (const float4*)d_in[1];   // [1, 4608, 2, 32, 16]
    float* out = (float*)d_out;                 // [128, 2, 32]

    cudaFuncSetAttribute(pass0_mma,
                         cudaFuncAttributeMaxDynamicSharedMemorySize, DSM_BYTES);
    cudaFuncSetAttribute(routing_mma,
                         cudaFuncAttributeMaxDynamicSharedMemorySize, DSM_BYTES);

    cudaLaunchAttribute pdl{};
    pdl.id = cudaLaunchAttributeProgrammaticStreamSerialization;
    pdl.val.programmaticStreamSerializationAllowed = 1;

    // first kernel: plain launch
    pass0_mma<<<NCTA, 512, DSM_BYTES>>>(x, W);

    {   // squash 0
        cudaLaunchConfig_t c = make_cfg(dim3(128), dim3(1024), 0, &pdl);
        int mode = 0; float* o = nullptr;
        if (cudaLaunchKernelEx(&c, squash_kernel, mode, o) != cudaSuccess)
            squash_kernel<<<128, 1024>>>(0, nullptr);
    }
    {   // routing 0
        cudaLaunchConfig_t c = make_cfg(dim3(NCTA), dim3(512), DSM_BYTES, &pdl);
        int pass = 0;
        if (cudaLaunchKernelEx(&c, routing_mma, x, W, pass) != cudaSuccess)
            routing_mma<<<NCTA, 512, DSM_BYTES>>>(x, W, 0);
    }
    {   // squash 1
        cudaLaunchConfig_t c = make_cfg(dim3(128), dim3(1024), 0, &pdl);
        int mode = 1; float* o = nullptr;
        if (cudaLaunchKernelEx(&c, squash_kernel, mode, o) != cudaSuccess)
            squash_kernel<<<128, 1024>>>(1, nullptr);
    }
    {   // routing 1
        cudaLaunchConfig_t c = make_cfg(dim3(NCTA), dim3(512), DSM_BYTES, &pdl);
        int pass = 1;
        if (cudaLaunchKernelEx(&c, routing_mma, x, W, pass) != cudaSuccess)
            routing_mma<<<NCTA, 512, DSM_BYTES>>>(x, W, 1);
    }
    {   // squash 2
        cudaLaunchConfig_t c = make_cfg(dim3(128), dim3(1024), 0, &pdl);
        int mode = 2;
        if (cudaLaunchKernelEx(&c, squash_kernel, mode, out) != cudaSuccess)
            squash_kernel<<<128, 1024>>>(2, out);
    }
}